// round 13
// baseline (speedup 1.0000x reference)
#include <cuda_runtime.h>
#include <cuda_bf16.h>

// Problem constants (S=8192, G=1024, T=4096, E=16384)
#define E_N 16384
#define T_N 4096
#define G_N 1024
#define CHUNK 32
#define NCHUNKS 128             // T / CHUNK
#define NBLK 128
#define NTHR 1024
#define G4 (G_N / 4)            // 256 group-quads
#define MWORDS 32               // 1024 groups / 32 bits
#define NTILES 16               // event tiles of 1024, work-stolen
#define SBUF 5120               // floats: t0 search / carry + totals

// Row-granular diff image [T][G]; read/zeroed sparsely via occupancy mask.
__device__ float g_rowdiff[T_N * G_N];
__device__ unsigned g_mask[T_N * MWORDS];        // 512 KB occupancy bits
// Chunk-granular diff, TRANSPOSED [group][chunk] (contiguous phase-B rows).
__device__ float g_cdiff[G_N * NCHUNKS];         // zeroed behind phase-B read
// Carry at each chunk start, [chunk][group] (fully rewritten each launch).
__device__ float g_carry[NCHUNKS * G_N];

// Work-stealing tile counter (reset by barrier-1 releaser each launch).
__device__ unsigned g_work;
// Grid barrier state (monotonic generation counter -> graph-replay-safe).
__device__ unsigned g_bar_arrive;
__device__ volatile unsigned g_bar_gen;

// One gpu-scope fence per CTA per side (scope promotion through bar.sync).
// reset_work: barrier-1 releaser also clears the tile counter (all grabs are
// complete once every CTA has arrived, so this is race-free).
__device__ __forceinline__ void grid_barrier(bool reset_work) {
    __syncthreads();
    if (threadIdx.x == 0) {
        __threadfence();
        unsigned gen = g_bar_gen;
        if (atomicAdd(&g_bar_arrive, 1) == NBLK - 1) {
            g_bar_arrive = 0;
            if (reset_work) g_work = 0;
            __threadfence();
            g_bar_gen = gen + 1;           // release
        } else {
            while (g_bar_gen == gen) { }   // poll (L2)
        }
        __threadfence();
    }
    __syncthreads();
}

__device__ __forceinline__ float4 ldcg4(const float4* p) { return __ldcg(p); }
__device__ __forceinline__ void stcg4(float4* p, float4 v) { __stcg(p, v); }

// ---------------------------------------------------------------------------
// Persistent kernel: 128 CTAs x 1024 threads (1 CTA/SM, single wave).
// Phase A is WORK-STOLEN: earliest-dispatched CTAs process all 16 event
// tiles while the rest of the grid is still ramping; late CTAs skip the
// t0 preload and search entirely and go straight to barrier 1.
// ---------------------------------------------------------------------------
__global__ void __launch_bounds__(NTHR, 1)
fused_kernel(const int*   __restrict__ index,
             const float* __restrict__ rate,
             const float* __restrict__ start,
             const float* __restrict__ endt,
             const float* __restrict__ t0,
             const int*   __restrict__ group_id,
             const float* __restrict__ weights,
             float*       __restrict__ out) {
    __shared__ float    s_buf[SBUF];             // 20 KB
    __shared__ unsigned s_mask[CHUNK * MWORDS];  // 4 KB
    __shared__ int      s_tile;
    const int tid = threadIdx.x;
    const int blk = blockIdx.x;

    // ---------------- Phase A: work-stolen event tiles ---------------------
    bool loaded = false;
    for (;;) {
        if (tid == 0) s_tile = (int)atomicAdd(&g_work, 1u);
        __syncthreads();
        const int t = s_tile;
        if (t >= NTILES) break;

        if (!loaded) {                      // t0 -> s_buf[0..4095], once
            ((float4*)s_buf)[tid] = ((const float4*)t0)[tid];
            loaded = true;
        }
        // Event loads overlap the preload (independent chains).
        const int e = t * NTHR + tid;
        const float st  = __ldg(&start[e]);
        const float en  = __ldg(&endt[e]);
        const int   src = __ldg(&index[e]);
        const float rt  = __ldg(&rate[e]);
        const float wsc = __ldg(&weights[src]);
        const int   g   = __ldg(&group_id[src]);
        __syncthreads();                    // preload visible (no-op later)

        // Branchless dual lower_bound over sorted t0 (4096 = 2^12).
        int a = 0, b = 0;
        #pragma unroll
        for (int s = T_N >> 1; s; s >>= 1) {
            a += (s_buf[a + s - 1] < st) ? s : 0;
            b += (s_buf[b + s - 1] < en) ? s : 0;
        }
        a += (s_buf[a] < st) ? 1 : 0;       // ts
        b += (s_buf[b] < en) ? 1 : 0;       // te

        const int ts = a, te = b;
        if (te > ts) {
            const float w = rt * wsc;
            const unsigned bit = 1u << (g & 31);
            if (ts & (CHUNK - 1)) {         // row-level residues (REDs)
                atomicAdd(&g_rowdiff[ts * G_N + g],  w);
                atomicOr (&g_mask[ts * MWORDS + (g >> 5)], bit);
            }
            if ((te & (CHUNK - 1)) && te < T_N) {
                atomicAdd(&g_rowdiff[te * G_N + g], -w);
                atomicOr (&g_mask[te * MWORDS + (g >> 5)], bit);
            }
            const int c0 = (ts + CHUNK - 1) >> 5;   // chunk-level diff
            const int c1 = (te + CHUNK - 1) >> 5;
            if (c0 != c1) {
                if (c0 < NCHUNKS) atomicAdd(&g_cdiff[g * NCHUNKS + c0],  w);
                if (c1 < NCHUNKS) atomicAdd(&g_cdiff[g * NCHUNKS + c1], -w);
            }
        }
        __syncthreads();                    // s_tile consumed by all
    }

    grid_barrier(true);   // barrier 1: scatters visible; work counter reset

    // ---------------- Mask slice + sparse rowdiff prefetch -----------------
    const int qid = tid & (G4 - 1);        // group-quad 0..255
    const int rb  = tid >> 8;              // row-group 0..3 (8 rows each)
    const int tbeg = blk * CHUNK;

    s_mask[tid] = __ldcg(&g_mask[tbeg * MWORDS + tid]);  // 4 KB coalesced

    // ---------------- Phase B: chunk-level prefix -> carry -----------------
    // Warp per group (8 groups per block): lane owns 4 consecutive chunks.
    {
        const int wid = tid >> 5, lid = tid & 31;
        if (wid < 8) {
            const int grp = blk * 8 + wid;
            float4* row = (float4*)g_cdiff + grp * (NCHUNKS / 4);
            float4 c4 = ldcg4(row + lid);
            const float s1 = c4.x, s2 = s1 + c4.y, s3 = s2 + c4.z, s4 = s3 + c4.w;
            float sum = s4;                 // warp inclusive scan of lane sums
            #pragma unroll
            for (int o = 1; o < 32; o <<= 1) {
                float n = __shfl_up_sync(0xffffffffu, sum, o);
                if (lid >= o) sum += n;
            }
            const float off = sum - s4;     // exclusive prefix
            const int c = lid * 4;
            __stcg(&g_carry[(c + 0) * G_N + grp], off + s1);
            __stcg(&g_carry[(c + 1) * G_N + grp], off + s2);
            __stcg(&g_carry[(c + 2) * G_N + grp], off + s3);
            __stcg(&g_carry[(c + 3) * G_N + grp], off + s4);
            stcg4(row + lid, make_float4(0.f, 0.f, 0.f, 0.f));  // replay-clean
        }
    }
    __syncthreads();   // s_mask ready; s_buf reusable

    // Sparse rowdiff load (nibble of the quad's mask word) + local scan.
    const int wix = qid >> 3;
    const int nsh = (qid & 7) * 4;
    float4 v[8];
    unsigned nz[8];
    #pragma unroll
    for (int i = 0; i < 8; i++) {
        nz[i] = (s_mask[(rb * 8 + i) * MWORDS + wix] >> nsh) & 0xFu;
        v[i] = nz[i] ? ldcg4((const float4*)g_rowdiff +
                             (size_t)(tbeg + rb * 8 + i) * G4 + qid)
                     : make_float4(0.f, 0.f, 0.f, 0.f);
    }
    float4 run = make_float4(0.f, 0.f, 0.f, 0.f);
    #pragma unroll
    for (int i = 0; i < 8; i++) {           // in-place inclusive scan
        run.x += v[i].x; run.y += v[i].y; run.z += v[i].z; run.w += v[i].w;
        v[i] = run;
    }
    // Row-group totals: s_buf floats [1024 .. 5119] (in-bounds, SBUF=5120).
    ((float4*)(s_buf + G_N))[rb * G4 + qid] = run;

    grid_barrier(false);  // barrier 2: carry globally visible

    // ---------------- Emit + sparse cleanup --------------------------------
    {
        float4 base = ldcg4((const float4*)&g_carry[blk * G_N] + qid);
        #pragma unroll
        for (int r = 0; r < 3; r++) {               // cross row-group prefix
            if (r < rb) {
                float4 tt = ((const float4*)(s_buf + G_N))[r * G4 + qid];
                base.x += tt.x; base.y += tt.y; base.z += tt.z; base.w += tt.w;
            }
        }
        float4* out4 = (float4*)out;
        float4* rdw4 = (float4*)g_rowdiff;
        const float4 z = make_float4(0.f, 0.f, 0.f, 0.f);
        #pragma unroll
        for (int i = 0; i < 8; i++) {
            float4 o;
            o.x = base.x + v[i].x;
            o.y = base.y + v[i].y;
            o.z = base.z + v[i].z;
            o.w = base.w + v[i].w;
            const size_t idx = (size_t)(tbeg + rb * 8 + i) * G4 + qid;
            stcg4(out4 + idx, o);
            if (nz[i]) stcg4(rdw4 + idx, z);        // sparse replay-clean
        }
        __stcg(&g_mask[tbeg * MWORDS + tid], 0u);   // mask replay-clean
    }
}

// ---------------------------------------------------------------------------
extern "C" void kernel_launch(void* const* d_in, const int* in_sizes, int n_in,
                              void* d_out, int out_size) {
    const int*   index    = (const int*)  d_in[0];
    const float* rate     = (const float*)d_in[1];
    const float* start    = (const float*)d_in[2];
    const float* endt     = (const float*)d_in[3];
    const float* t0       = (const float*)d_in[4];
    const int*   group_id = (const int*)  d_in[5];
    const float* weights  = (const float*)d_in[6];
    float* out = (float*)d_out;

    fused_kernel<<<NBLK, NTHR>>>(index, rate, start, endt, t0,
                                 group_id, weights, out);
}

// round 15
// speedup vs baseline: 2.2055x; 2.2055x over previous
#include <cuda_runtime.h>
#include <cuda_bf16.h>

// Problem constants (S=8192, G=1024, T=4096, E=16384)
#define E_N 16384
#define T_N 4096
#define G_N 1024
#define CHUNK 32
#define NCHUNKS 128             // T / CHUNK
#define G4 (G_N / 4)            // 256 group-quads
#define MWORDS 32               // 1024 groups / 32 bits

// Row-granular diff image [T][G]; read/zeroed sparsely via occupancy mask.
__device__ float g_rowdiff[T_N * G_N];
__device__ unsigned g_mask[T_N * MWORDS];        // 512 KB occupancy bits
// Chunk-granular diff, TRANSPOSED [group][chunk] (contiguous K2 rows).
__device__ float g_cdiff[G_N * NCHUNKS];         // zeroed behind K2's read
// Carry at each chunk start, [chunk][group] (fully rewritten each launch).
__device__ float g_carry[NCHUNKS * G_N];

__device__ __forceinline__ float4 ldcg4(const float4* p) { return __ldcg(p); }
__device__ __forceinline__ void stcg4(float4* p, float4 v) { __stcg(p, v); }

// ---------------------------------------------------------------------------
// K1: event scatter. 128 blocks x 128 threads, 1 event/thread.
// Branchless dual lower_bound over smem t0; all scatters are fire-and-forget
// REDs (no returning atomics anywhere).
// ---------------------------------------------------------------------------
__global__ void __launch_bounds__(128)
k1_scatter(const int*   __restrict__ index,
           const float* __restrict__ rate,
           const float* __restrict__ start,
           const float* __restrict__ endt,
           const float* __restrict__ t0,
           const int*   __restrict__ group_id,
           const float* __restrict__ weights) {
    __shared__ float s_t0[T_N];            // 16 KB
    const int tid = threadIdx.x;
    {
        float4* s4 = (float4*)s_t0;
        const float4* t4 = (const float4*)t0;
        #pragma unroll
        for (int i = 0; i < T_N / 4 / 128; i++)    // 8 float4 per thread
            s4[i * 128 + tid] = t4[i * 128 + tid];
    }

    const int e = blockIdx.x * 128 + tid;
    // Hoisted scalar loads overlap the preload.
    const float st  = __ldg(&start[e]);
    const float en  = __ldg(&endt[e]);
    const int   src = __ldg(&index[e]);
    const float rt  = __ldg(&rate[e]);
    const float wsc = __ldg(&weights[src]);
    const int   g   = __ldg(&group_id[src]);
    __syncthreads();

    // Branchless dual lower_bound (t0 sorted, 4096 = 2^12), interleaved.
    int a = 0, b = 0;
    #pragma unroll
    for (int s = T_N >> 1; s; s >>= 1) {
        a += (s_t0[a + s - 1] < st) ? s : 0;
        b += (s_t0[b + s - 1] < en) ? s : 0;
    }
    a += (s_t0[a] < st) ? 1 : 0;           // ts
    b += (s_t0[b] < en) ? 1 : 0;           // te

    const int ts = a, te = b;
    if (te <= ts) return;

    const float w = rt * wsc;
    const unsigned bit = 1u << (g & 31);
    // Row-level residues + occupancy bits.
    if (ts & (CHUNK - 1)) {
        atomicAdd(&g_rowdiff[ts * G_N + g],  w);
        atomicOr (&g_mask[ts * MWORDS + (g >> 5)], bit);
    }
    if ((te & (CHUNK - 1)) && te < T_N) {
        atomicAdd(&g_rowdiff[te * G_N + g], -w);
        atomicOr (&g_mask[te * MWORDS + (g >> 5)], bit);
    }
    // Chunk-level diff (transposed layout).
    const int c0 = (ts + CHUNK - 1) >> 5;
    const int c1 = (te + CHUNK - 1) >> 5;
    if (c0 != c1) {
        if (c0 < NCHUNKS) atomicAdd(&g_cdiff[g * NCHUNKS + c0],  w);
        if (c1 < NCHUNKS) atomicAdd(&g_cdiff[g * NCHUNKS + c1], -w);
    }
}

// ---------------------------------------------------------------------------
// K2: chunk-level prefix -> carry. Warp per group (1024 warps total):
// lane owns 4 consecutive chunks of the contiguous transposed row; shfl scan;
// zero cdiff behind the read (replay-clean).
// ---------------------------------------------------------------------------
__global__ void __launch_bounds__(256)
k2_scan() {
    const int wid = threadIdx.x >> 5, lid = threadIdx.x & 31;
    const int grp = blockIdx.x * 8 + wid;        // 128 blocks x 8 warps
    float4* row = (float4*)g_cdiff + grp * (NCHUNKS / 4);
    float4 c4 = ldcg4(row + lid);
    const float s1 = c4.x, s2 = s1 + c4.y, s3 = s2 + c4.z, s4 = s3 + c4.w;
    float sum = s4;
    #pragma unroll
    for (int o = 1; o < 32; o <<= 1) {
        float n = __shfl_up_sync(0xffffffffu, sum, o);
        if (lid >= o) sum += n;
    }
    const float off = sum - s4;                  // exclusive prefix
    const int c = lid * 4;
    __stcg(&g_carry[(c + 0) * G_N + grp], off + s1);
    __stcg(&g_carry[(c + 1) * G_N + grp], off + s2);
    __stcg(&g_carry[(c + 2) * G_N + grp], off + s3);
    __stcg(&g_carry[(c + 3) * G_N + grp], off + s4);
    stcg4(row + lid, make_float4(0.f, 0.f, 0.f, 0.f));   // replay-clean
}

// ---------------------------------------------------------------------------
// K3: per-chunk emit. 128 blocks x 1024 threads. Sparse mask-driven rowdiff
// read, register scan, cross-row-group prefix via smem, coalesced STG.128
// output, sparse cleanup.
// ---------------------------------------------------------------------------
__global__ void __launch_bounds__(1024, 1)
k3_emit(float* __restrict__ out) {
    __shared__ float    s_tot[4 * G_N];          // 16 KB row-group totals
    __shared__ unsigned s_mask[CHUNK * MWORDS];  // 4 KB
    const int tid = threadIdx.x;
    const int blk = blockIdx.x;
    const int qid = tid & (G4 - 1);              // group-quad 0..255
    const int rb  = tid >> 8;                    // row-group 0..3 (8 rows)
    const int tbeg = blk * CHUNK;

    s_mask[tid] = __ldcg(&g_mask[tbeg * MWORDS + tid]);
    // Carry quad prefetch (written by K2, prior kernel -> visible).
    float4 base = ldcg4((const float4*)&g_carry[blk * G_N] + qid);
    __syncthreads();

    const int wix = qid >> 3;
    const int nsh = (qid & 7) * 4;
    float4 v[8];
    unsigned nz[8];
    #pragma unroll
    for (int i = 0; i < 8; i++) {
        nz[i] = (s_mask[(rb * 8 + i) * MWORDS + wix] >> nsh) & 0xFu;
        v[i] = nz[i] ? ldcg4((const float4*)g_rowdiff +
                             (size_t)(tbeg + rb * 8 + i) * G4 + qid)
                     : make_float4(0.f, 0.f, 0.f, 0.f);
    }
    float4 run = make_float4(0.f, 0.f, 0.f, 0.f);
    #pragma unroll
    for (int i = 0; i < 8; i++) {                // in-place inclusive scan
        run.x += v[i].x; run.y += v[i].y; run.z += v[i].z; run.w += v[i].w;
        v[i] = run;
    }
    ((float4*)s_tot)[rb * G4 + qid] = run;
    __syncthreads();

    #pragma unroll
    for (int r = 0; r < 3; r++) {                // cross row-group prefix
        if (r < rb) {
            float4 t = ((const float4*)s_tot)[r * G4 + qid];
            base.x += t.x; base.y += t.y; base.z += t.z; base.w += t.w;
        }
    }
    float4* out4 = (float4*)out;
    float4* rdw4 = (float4*)g_rowdiff;
    const float4 z = make_float4(0.f, 0.f, 0.f, 0.f);
    #pragma unroll
    for (int i = 0; i < 8; i++) {
        float4 o;
        o.x = base.x + v[i].x;
        o.y = base.y + v[i].y;
        o.z = base.z + v[i].z;
        o.w = base.w + v[i].w;
        const size_t idx = (size_t)(tbeg + rb * 8 + i) * G4 + qid;
        stcg4(out4 + idx, o);
        if (nz[i]) stcg4(rdw4 + idx, z);         // sparse replay-clean
    }
    __stcg(&g_mask[tbeg * MWORDS + tid], 0u);    // mask replay-clean
}

// ---------------------------------------------------------------------------
extern "C" void kernel_launch(void* const* d_in, const int* in_sizes, int n_in,
                              void* d_out, int out_size) {
    const int*   index    = (const int*)  d_in[0];
    const float* rate     = (const float*)d_in[1];
    const float* start    = (const float*)d_in[2];
    const float* endt     = (const float*)d_in[3];
    const float* t0       = (const float*)d_in[4];
    const int*   group_id = (const int*)  d_in[5];
    const float* weights  = (const float*)d_in[6];
    float* out = (float*)d_out;

    k1_scatter<<<E_N / 128, 128>>>(index, rate, start, endt, t0,
                                   group_id, weights);
    k2_scan<<<G_N / 8, 256>>>();
    k3_emit<<<NCHUNKS, 1024>>>(out);
}